// round 12
// baseline (speedup 1.0000x reference)
#include <cuda_runtime.h>
#include <cuda_bf16.h>
#include <math.h>
#include <math_constants.h>
#include <cstdint>

// Problem constants
#define NB 2
#define NS 2048
#define ND 2048
#define NH 16
#define DH 128
#define NM 4096   // NB*NS

#define L2_10K_OVER_64 0.2076205059304602f   // log2(10000)/64
#define QSCALE 0.08838834764831845f          // 1/sqrt(128)

// Scratch: sanctioned __device__ globals (no runtime allocation).
__device__ __nv_bfloat16 g_xh [NM*ND];         // attn-out hi (flash output)
__device__ __nv_bfloat16 g_xl [NM*ND];         // attn-out lo
__device__ __nv_bfloat16 g_wh [ND*ND];         // Wo^T hi [n][k] (bf16 path)
__device__ __nv_bfloat16 g_wl [ND*ND];         // Wo^T lo
__device__ __nv_bfloat16 g_qh [NB*NH*NS*DH];   // Q hi  (B,H,S,D), roped+scaled
__device__ __nv_bfloat16 g_ql [NB*NH*NS*DH];
__device__ __nv_bfloat16 g_kh [NB*NH*NS*DH];   // K hi  (B,H,S,D), roped
__device__ __nv_bfloat16 g_kl [NB*NH*NS*DH];
__device__ __nv_bfloat16 g_vth[NB*NH*DH*NS];   // V^T hi (B,H,D,S)
__device__ __nv_bfloat16 g_vtl[NB*NH*DH*NS];
// int8 path (Q/K/V projections)
__device__ char  g_ah8[NM*ND];                 // x limb hi (s8)
__device__ char  g_al8[NM*ND];                 // x limb lo (s8)
__device__ float g_sa [NM];                    // per-row scale of x
__device__ char  g_wh8[3*ND*ND];               // Wq/Wk/Wv ^T limb hi [w][n][k]
__device__ char  g_wl8[3*ND*ND];
__device__ float g_ws [3*ND];                  // per-output-col scale

struct OutPtrs {
    __nv_bfloat16 *qh, *ql, *kh, *kl, *vth, *vtl;
};

// ============================ PTX helpers ==================================
__device__ __forceinline__ uint32_t smem_u32(const void* p) {
    uint32_t a;
    asm("{ .reg .u64 t; cvta.to.shared.u64 t, %1; cvt.u32.u64 %0, t; }"
        : "=r"(a) : "l"(p));
    return a;
}

__device__ __forceinline__ void ldsm4(uint32_t* r, uint32_t addr) {
    asm volatile("ldmatrix.sync.aligned.m8n8.x4.shared.b16 {%0,%1,%2,%3}, [%4];"
        : "=r"(r[0]), "=r"(r[1]), "=r"(r[2]), "=r"(r[3]) : "r"(addr));
}

__device__ __forceinline__ void mma_bf16(float* c, const uint32_t* a,
                                         uint32_t b0, uint32_t b1) {
    asm volatile(
        "mma.sync.aligned.m16n8k16.row.col.f32.bf16.bf16.f32 "
        "{%0,%1,%2,%3}, {%4,%5,%6,%7}, {%8,%9}, {%0,%1,%2,%3};"
        : "+f"(c[0]), "+f"(c[1]), "+f"(c[2]), "+f"(c[3])
        : "r"(a[0]), "r"(a[1]), "r"(a[2]), "r"(a[3]), "r"(b0), "r"(b1));
}

__device__ __forceinline__ void mma_s8(int* c, const uint32_t* a,
                                       uint32_t b0, uint32_t b1) {
    asm volatile(
        "mma.sync.aligned.m16n8k32.row.col.s32.s8.s8.s32 "
        "{%0,%1,%2,%3}, {%4,%5,%6,%7}, {%8,%9}, {%0,%1,%2,%3};"
        : "+r"(c[0]), "+r"(c[1]), "+r"(c[2]), "+r"(c[3])
        : "r"(a[0]), "r"(a[1]), "r"(a[2]), "r"(a[3]), "r"(b0), "r"(b1));
}

__device__ __forceinline__ void cpa16(uint32_t saddr, const void* gaddr) {
    asm volatile("cp.async.cg.shared.global [%0], [%1], 16;"
                 :: "r"(saddr), "l"(gaddr));
}
#define CPA_COMMIT() asm volatile("cp.async.commit_group;")
#define CPA_WAIT1()  asm volatile("cp.async.wait_group 1;")
#define CPA_WAIT0()  asm volatile("cp.async.wait_group 0;")

// pack (a,b) into bf16x2 hi word + bf16x2 lo-residual word
__device__ __forceinline__ void hilo2(float a, float b, uint32_t& hi, uint32_t& lo) {
    __nv_bfloat16 ha = __float2bfloat16_rn(a);
    __nv_bfloat16 hb = __float2bfloat16_rn(b);
    __nv_bfloat162 hp(ha, hb);
    __nv_bfloat162 lp = __floats2bfloat162_rn(a - __bfloat162float(ha),
                                              b - __bfloat162float(hb));
    hi = *reinterpret_cast<uint32_t*>(&hp);
    lo = *reinterpret_cast<uint32_t*>(&lp);
}

__device__ __forceinline__ int clamp127(int v) {
    return v > 127 ? 127 : (v < -127 ? -127 : v);
}

// =========================== prep kernels ==================================
// Row-wise two-limb int8 quantization of x: x ~ s*(h + l/256)
__global__ void __launch_bounds__(256) quant_rows(const float* __restrict__ in,
                                                  char* __restrict__ h8,
                                                  char* __restrict__ l8,
                                                  float* __restrict__ sc) {
    const int lane = threadIdx.x & 31;
    const int row  = blockIdx.x * 8 + (threadIdx.x >> 5);
    const float* rp = in + (size_t)row * ND;
    float mx = 0.f;
    for (int i = lane * 4; i < ND; i += 128) {
        float4 v = *(const float4*)(rp + i);
        mx = fmaxf(mx, fmaxf(fmaxf(fabsf(v.x), fabsf(v.y)),
                             fmaxf(fabsf(v.z), fabsf(v.w))));
    }
#pragma unroll
    for (int off = 16; off; off >>= 1)
        mx = fmaxf(mx, __shfl_xor_sync(0xffffffffu, mx, off));
    const float s   = mx * (1.f / 127.f);
    const float inv = 127.f / mx;
    if (lane == 0) sc[row] = s;
    for (int i = lane * 4; i < ND; i += 128) {
        float4 v = *(const float4*)(rp + i);
        int h0 = __float2int_rn(v.x * inv);
        int h1 = __float2int_rn(v.y * inv);
        int h2 = __float2int_rn(v.z * inv);
        int h3 = __float2int_rn(v.w * inv);
        float sc256 = inv * 256.f;
        int l0 = clamp127(__float2int_rn((v.x - h0 * s) * sc256));
        int l1 = clamp127(__float2int_rn((v.y - h1 * s) * sc256));
        int l2 = clamp127(__float2int_rn((v.z - h2 * s) * sc256));
        int l3 = clamp127(__float2int_rn((v.w - h3 * s) * sc256));
        uint32_t hp = (h0 & 255) | ((h1 & 255) << 8) | ((h2 & 255) << 16) | ((uint32_t)(h3 & 255) << 24);
        uint32_t lp = (l0 & 255) | ((l1 & 255) << 8) | ((l2 & 255) << 16) | ((uint32_t)(l3 & 255) << 24);
        *(uint32_t*)(h8 + (size_t)row * ND + i) = hp;
        *(uint32_t*)(l8 + (size_t)row * ND + i) = lp;
    }
}

// Per-column abs-max of Wq/Wk/Wv -> per-output-col scale
__global__ void __launch_bounds__(256) colmax_w(const float* __restrict__ W0,
                                                const float* __restrict__ W1,
                                                const float* __restrict__ W2,
                                                float* __restrict__ ws) {
    const int n = blockIdx.x * 256 + threadIdx.x;
    const int w = blockIdx.y;
    const float* W = (w == 0) ? W0 : (w == 1) ? W1 : W2;
    float mx = 0.f;
    for (int k = 0; k < ND; k += 4) {
        mx = fmaxf(mx, fabsf(W[(size_t)k * ND + n]));
        mx = fmaxf(mx, fabsf(W[(size_t)(k + 1) * ND + n]));
        mx = fmaxf(mx, fabsf(W[(size_t)(k + 2) * ND + n]));
        mx = fmaxf(mx, fabsf(W[(size_t)(k + 3) * ND + n]));
    }
    ws[w * ND + n] = mx * (1.f / 127.f);
}

// Transpose all four weights; w<3 -> int8 limbs (scaled), w==3 -> bf16 hi/lo
__global__ void __launch_bounds__(256) quant_wT4(
    const float* __restrict__ W0, const float* __restrict__ W1,
    const float* __restrict__ W2, const float* __restrict__ W3,
    char* __restrict__ th8, char* __restrict__ tl8, const float* __restrict__ ws,
    __nv_bfloat16* __restrict__ thB, __nv_bfloat16* __restrict__ tlB) {
    __shared__ float t[32][33];
    const int w  = blockIdx.z;
    const float* W = (w == 0) ? W0 : (w == 1) ? W1 : (w == 2) ? W2 : W3;
    const int bx = blockIdx.x * 32;   // n tile
    const int by = blockIdx.y * 32;   // k tile
    const int tx = threadIdx.x, ty = threadIdx.y;
#pragma unroll
    for (int j = ty; j < 32; j += 8)
        t[j][tx] = W[(size_t)(by + j) * ND + bx + tx];
    __syncthreads();
#pragma unroll
    for (int j = ty; j < 32; j += 8) {
        float v = t[tx][j];           // = W[by+tx][bx+j]; out row n=bx+j, col k=by+tx
        if (w < 3) {
            float s   = ws[w * ND + bx + j];
            float inv = 1.f / s;
            int h = __float2int_rn(v * inv);
            int l = clamp127(__float2int_rn((v - h * s) * inv * 256.f));
            th8[(size_t)w * ND * ND + (size_t)(bx + j) * ND + by + tx] = (char)h;
            tl8[(size_t)w * ND * ND + (size_t)(bx + j) * ND + by + tx] = (char)l;
        } else {
            __nv_bfloat16 h = __float2bfloat16_rn(v);
            __nv_bfloat16 l = __float2bfloat16_rn(v - __bfloat162float(h));
            thB[(size_t)(bx + j) * ND + by + tx] = h;
            tlB[(size_t)(bx + j) * ND + by + tx] = l;
        }
    }
}

// ================ int8x3 Q/K/V projection GEMM (mma.s8) ====================
// C = x @ Wt^T via s*(h + l/256) limbs; acc1 = hh, acc2 = hl + lh.
// CTA 128x64, 8 warps (warp 32x32), k-block 64, cp.async double buffer.
#define I8PITCH 80                         // 64 s8 + 16 pad
#define ATILE8  (128 * I8PITCH)            // 10240
#define BTILE8  (64 * I8PITCH)             // 5120
#define STG8    (2 * ATILE8 + 2 * BTILE8)  // 30720
#define GSMEM8  (2 * STG8)                 // 61440

__global__ void __launch_bounds__(256, 2) gemm_qkv8(
    const char* __restrict__ Ah8, const char* __restrict__ Al8,
    const char* __restrict__ Wh8, const char* __restrict__ Wl8,
    const float* __restrict__ sa, const float* __restrict__ ws,
    OutPtrs op)
{
    extern __shared__ char smc[];
    const uint32_t sbase = smem_u32(smc);
    const int tid  = threadIdx.x;
    const int wid  = tid >> 5;
    const int lane = tid & 31;
    const int wm   = wid & 3;                    // 4 m-groups of 32
    const int wn   = wid >> 2;                   // 2 n-groups of 32
    const int mode = blockIdx.x >> 5;            // 0=Q 1=K 2=V
    const int col0 = (blockIdx.x & 31) * 64;
    const int row0 = blockIdx.y * 128;

    const char* Ab = Ah8 + (size_t)row0 * ND;
    const char* Lb = Al8 + (size_t)row0 * ND;
    const char* Bb = Wh8 + (size_t)mode * ND * ND + (size_t)col0 * ND;
    const char* Cb = Wl8 + (size_t)mode * ND * ND + (size_t)col0 * ND;

    auto load_stage = [&](int buf, int k0) {
#pragma unroll
        for (int t = 0; t < 6; ++t) {
            int id = tid + t * 256;              // 0..1535 16B chunks
            uint32_t so;
            const char* g;
            if (id < 1024) {                     // A limbs: 512 chunks each
                int limb = id >> 9, rem = id & 511;
                int r = rem >> 2, c = rem & 3;
                so = sbase + buf * STG8 + limb * ATILE8 + r * I8PITCH + c * 16;
                g  = (limb ? Lb : Ab) + (size_t)r * ND + k0 + c * 16;
            } else {                             // B limbs: 256 chunks each
                int id2 = id - 1024;
                int limb = id2 >> 8, rem = id2 & 255;
                int r = rem >> 2, c = rem & 3;
                so = sbase + buf * STG8 + 2 * ATILE8 + limb * BTILE8
                   + r * I8PITCH + c * 16;
                g  = (limb ? Cb : Bb) + (size_t)r * ND + k0 + c * 16;
            }
            cpa16(so, g);
        }
        CPA_COMMIT();
    };

    int acc1[2][4][4], acc2[2][4][4];
#pragma unroll
    for (int mf = 0; mf < 2; ++mf)
#pragma unroll
        for (int nf = 0; nf < 4; ++nf)
#pragma unroll
            for (int e = 0; e < 4; ++e) { acc1[mf][nf][e] = 0; acc2[mf][nf][e] = 0; }

    load_stage(0, 0);

    for (int it = 0; it < 32; ++it) {
        const int buf = it & 1;
        if (it + 1 < 32) { load_stage(buf ^ 1, (it + 1) * 64); CPA_WAIT1(); }
        else             { CPA_WAIT0(); }
        __syncthreads();

        const uint32_t sA  = sbase + buf * STG8;
        const uint32_t sAl = sA + ATILE8;
        const uint32_t sB  = sA + 2 * ATILE8;
        const uint32_t sBl = sB + BTILE8;

#pragma unroll
        for (int ks = 0; ks < 2; ++ks) {         // two k32 sub-steps
            const int akb = ks * 32 + (lane >> 4) * 16;
            uint32_t ah[2][4], al[2][4];
#pragma unroll
            for (int mf = 0; mf < 2; ++mf) {
                uint32_t ro = (wm * 32 + mf * 16 + (lane & 15)) * I8PITCH + akb;
                ldsm4(ah[mf], sA  + ro);
                ldsm4(al[mf], sAl + ro);
            }
            const int brow = wn * 32 + (lane & 7) + ((lane >> 4) << 3);
            const int bkb  = ks * 32 + ((lane >> 3) & 1) * 16;
#pragma unroll
            for (int nf2 = 0; nf2 < 2; ++nf2) {
                uint32_t bo = (brow + nf2 * 16) * I8PITCH + bkb;
                uint32_t bh[4], bl[4];
                ldsm4(bh, sB  + bo);
                ldsm4(bl, sBl + bo);
#pragma unroll
                for (int half = 0; half < 2; ++half) {
                    uint32_t h0 = bh[half * 2], h1 = bh[half * 2 + 1];
                    uint32_t l0 = bl[half * 2], l1 = bl[half * 2 + 1];
                    int nf = nf2 * 2 + half;
#pragma unroll
                    for (int mf = 0; mf < 2; ++mf) {
                        mma_s8(acc1[mf][nf], ah[mf], h0, h1);   // hh
                        mma_s8(acc2[mf][nf], ah[mf], l0, l1);   // h*l
                        mma_s8(acc2[mf][nf], al[mf], h0, h1);   // l*h
                    }
                }
            }
        }
        __syncthreads();
    }

    // ---- epilogue: dequant + rope/scale/layout (math identical to R10) ----
    __nv_bfloat16* Ch = (mode == 0) ? op.qh : (mode == 1) ? op.kh : op.vth;
    __nv_bfloat16* Cl = (mode == 0) ? op.ql : (mode == 1) ? op.kl : op.vtl;

    float sb[4][2];
#pragma unroll
    for (int nf = 0; nf < 4; ++nf) {
        int col = col0 + wn * 32 + nf * 8 + ((lane & 3) << 1);
        sb[nf][0] = ws[mode * ND + col];
        sb[nf][1] = ws[mode * ND + col + 1];
    }

#pragma unroll
    for (int mf = 0; mf < 2; ++mf) {
        const int mrow = row0 + wm * 32 + mf * 16 + (lane >> 2);
#pragma unroll
        for (int rr = 0; rr < 2; ++rr) {
            const int m  = mrow + rr * 8;
            const int bb = m >> 11, ss = m & 2047;
            const float s_am = sa[m];
#pragma unroll
            for (int nf = 0; nf < 4; ++nf) {
                const int cloc = wn * 32 + nf * 8 + ((lane & 3) << 1);
                const int col  = col0 + cloc;
                const int h    = col >> 7;
                const int d    = col & 127;
                float v0 = s_am * sb[nf][0] *
                    ((float)acc1[mf][nf][rr * 2 + 0] +
                     (float)acc2[mf][nf][rr * 2 + 0] * (1.f / 256.f));
                float v1 = s_am * sb[nf][1] *
                    ((float)acc1[mf][nf][rr * 2 + 1] +
                     (float)acc2[mf][nf][rr * 2 + 1] * (1.f / 256.f));
                if (mode == 2) {
                    size_t vb = ((size_t)(bb * NH + h) * DH + d) * NS + ss;
                    __nv_bfloat16 h0 = __float2bfloat16_rn(v0);
                    __nv_bfloat16 h1 = __float2bfloat16_rn(v1);
                    Ch[vb]      = h0;
                    Ch[vb + NS] = h1;
                    Cl[vb]      = __float2bfloat16_rn(v0 - __bfloat162float(h0));
                    Cl[vb + NS] = __float2bfloat16_rn(v1 - __bfloat162float(h1));
                } else {
                    size_t ob = (((size_t)(bb * NH + h) * NS + ss) << 7) + d;
                    float pos  = (float)ss;
                    float inv0 = exp2f(-(float)( d      & 63) * L2_10K_OVER_64);
                    float inv1 = exp2f(-(float)((d + 1) & 63) * L2_10K_OVER_64);
                    float s0, c0, s1, c1;
                    sincosf(pos * inv0, &s0, &c0);
                    sincosf(pos * inv1, &s1, &c1);
                    float o0 = v0 * c0 - v1 * s0;
                    float o1 = v1 * c1 + v0 * s1;
                    if (mode == 0) { o0 *= QSCALE; o1 *= QSCALE; }
                    uint32_t hp, lp;
                    hilo2(o0, o1, hp, lp);
                    *reinterpret_cast<uint32_t*>(Ch + ob) = hp;
                    *reinterpret_cast<uint32_t*>(Cl + ob) = lp;
                }
            }
        }
    }
}

// ===================== bf16x3 GEMM (final projection) ======================
#define APITCH 80
#define TILE_BYTES (128 * APITCH)
#define STAGE_BYTES (4 * TILE_BYTES)
#define GSMEM (2 * STAGE_BYTES)            // 81920

__device__ __forceinline__ void mma_mainloop(
    float acc[2][8][4],
    const __nv_bfloat16* __restrict__ ArowH, const __nv_bfloat16* __restrict__ ArowL,
    const __nv_bfloat16* __restrict__ BrowH, const __nv_bfloat16* __restrict__ BrowL,
    uint32_t sbase, int tid, int wm, int wn, int lane)
{
    auto load_stage = [&](int buf, int k0) {
#pragma unroll
        for (int t = 0; t < 8; ++t) {
            int id   = tid + t * 256;
            int tile = id >> 9;
            int rem  = id & 511;
            int r    = rem >> 2;
            int c    = rem & 3;
            uint32_t so = sbase + buf * STAGE_BYTES + tile * TILE_BYTES
                        + r * APITCH + c * 16;
            const __nv_bfloat16* g;
            if      (tile == 0) g = ArowH + (size_t)r * ND + k0 + c * 8;
            else if (tile == 1) g = ArowL + (size_t)r * ND + k0 + c * 8;
            else if (tile == 2) g = BrowH + (size_t)r * ND + k0 + c * 8;
            else                g = BrowL + (size_t)r * ND + k0 + c * 8;
            cpa16(so, g);
        }
        CPA_COMMIT();
    };

    load_stage(0, 0);

    for (int it = 0; it < 64; ++it) {
        const int buf = it & 1;
        if (it + 1 < 64) { load_stage(buf ^ 1, (it + 1) * 32); CPA_WAIT1(); }
        else             { CPA_WAIT0(); }
        __syncthreads();

        const uint32_t sA  = sbase + buf * STAGE_BYTES;
        const uint32_t sAl = sA + TILE_BYTES;
        const uint32_t sB  = sA + 2 * TILE_BYTES;
        const uint32_t sBl = sA + 3 * TILE_BYTES;

#pragma unroll
        for (int ks = 0; ks < 2; ++ks) {
            const int akb = ks * 32 + (lane >> 4) * 16;
            uint32_t ah[2][4], al[2][4];
#pragma unroll
            for (int mf = 0; mf < 2; ++mf) {
                uint32_t ro = (wm * 32 + mf * 16 + (lane & 15)) * APITCH + akb;
                ldsm4(ah[mf], sA  + ro);
                ldsm4(al[mf], sAl + ro);
            }
            const int brow = wn * 64 + (lane & 7) + ((lane >> 4) << 3);
            const int bkb  = ks * 32 + ((lane >> 3) & 1) * 16;
#pragma unroll
            for (int nf2 = 0; nf2 < 4; ++nf2) {
                uint32_t bo = (brow + nf2 * 16) * APITCH + bkb;
                uint32_t bh[4], bl[4];
                ldsm4(bh, sB  + bo);
                ldsm4(bl, sBl + bo);
#pragma unroll
                for (int half = 0; half < 2; ++half) {
                    uint32_t h0 = bh[half * 2], h1 = bh[half * 2 + 1];
                    uint32_t l0 = bl[half * 2], l1 = bl[half * 2 + 1];
                    int nf = nf2 * 2 + half;
#pragma unroll
                    for (int mf = 0; mf < 2; ++mf) {
                        mma_bf16(acc[mf][nf], ah[mf], h0, h1);
                        mma_bf16(acc[mf][nf], ah[mf], l0, l1);
                        mma_bf16(acc[mf][nf], al[mf], h0, h1);
                    }
                }
            }
        }
        __syncthreads();
    }
}

__global__ void __launch_bounds__(256, 2) gemm_out(
    const __nv_bfloat16* __restrict__ Ah, const __nv_bfloat16* __restrict__ Al,
    const __nv_bfloat16* __restrict__ Wh, const __nv_bfloat16* __restrict__ Wl,
    float* __restrict__ C)
{
    extern __shared__ char smc[];
    const uint32_t sbase = smem_u32(smc);
    const int tid  = threadIdx.x;
    const int wid  = tid >> 5;
    const int lane = tid & 31;
    const int wm   = wid & 3;
    const int wn   = wid >> 2;
    const int col0 = blockIdx.x * 128;
    const int row0 = blockIdx.y * 128;

    float acc[2][8][4];
#pragma unroll
    for (int mf = 0; mf < 2; ++mf)
#pragma unroll
        for (int nf = 0; nf < 8; ++nf)
#pragma unroll
            for (int e = 0; e < 4; ++e) acc[mf][nf][e] = 0.f;

    mma_mainloop(acc, Ah + (size_t)row0 * ND, Al + (size_t)row0 * ND,
                 Wh + (size_t)col0 * ND, Wl + (size_t)col0 * ND,
                 sbase, tid, wm, wn, lane);

#pragma unroll
    for (int mf = 0; mf < 2; ++mf) {
        const int mrow = row0 + wm * 32 + mf * 16 + (lane >> 2);
#pragma unroll
        for (int rr = 0; rr < 2; ++rr) {
            const int m = mrow + rr * 8;
#pragma unroll
            for (int nf = 0; nf < 8; ++nf) {
                const int col = col0 + wn * 64 + nf * 8 + ((lane & 3) << 1);
                *(float2*)(C + (size_t)m * ND + col) =
                    make_float2(acc[mf][nf][rr * 2 + 0], acc[mf][nf][rr * 2 + 1]);
            }
        }
    }
}

// ======================= flash attention (mma.sync) ========================
// Unchanged from round 10/11 (known-good).
#define QPB 272
#define VPB 144
#define OQH 0
#define OQL (OQH + 128*QPB)
#define OKH (OQL + 128*QPB)
#define OKL (OKH + 2*64*QPB)
#define OVH (OKL + 2*64*QPB)
#define OVL (OVH + 2*128*VPB)
#define FSMEM (OVL + 2*128*VPB)       // 212992

__global__ void __launch_bounds__(256, 1) flash_mma(
    const __nv_bfloat16* __restrict__ Qh, const __nv_bfloat16* __restrict__ Ql,
    const __nv_bfloat16* __restrict__ Kh, const __nv_bfloat16* __restrict__ Kl,
    const __nv_bfloat16* __restrict__ Vth, const __nv_bfloat16* __restrict__ Vtl,
    __nv_bfloat16* __restrict__ Oh, __nv_bfloat16* __restrict__ Ol)
{
    extern __shared__ char smc[];
    const uint32_t sb = smem_u32(smc);
    const int tid = threadIdx.x, wid = tid >> 5, lane = tid & 31;
    const int qt = gridDim.x - 1 - blockIdx.x;
    const int q0 = qt * 128;
    const int h  = blockIdx.y, b = blockIdx.z;
    const size_t ho = (size_t)(b * NH + h) * NS * DH;

#pragma unroll
    for (int t = 0; t < 16; ++t) {
        int id  = tid + t * 256;
        int arr = id >> 11;
        int rem = id & 2047;
        int r = rem >> 4, c = rem & 15;
        uint32_t so = sb + (arr ? OQL : OQH) + r * QPB + c * 16;
        const __nv_bfloat16* g = (arr ? Ql : Qh) + ho + (size_t)(q0 + r) * DH + c * 8;
        cpa16(so, g);
    }

    auto loadKV = [&](int buf, int n0) {
#pragma unroll
        for (int t = 0; t < 8; ++t) {
            int id  = tid + t * 256;
            int arr = id >> 10;
            int rem = id & 1023;
            int r = rem >> 4, c = rem & 15;
            uint32_t so = sb + (arr ? OKL : OKH) + buf * (64 * QPB) + r * QPB + c * 16;
            const __nv_bfloat16* g = (arr ? Kl : Kh) + ho + (size_t)(n0 + r) * DH + c * 8;
            cpa16(so, g);
        }
#pragma unroll
        for (int t = 0; t < 8; ++t) {
            int id  = tid + t * 256;
            int arr = id >> 10;
            int rem = id & 1023;
            int r = rem >> 3, c = rem & 7;
            uint32_t so = sb + (arr ? OVL : OVH) + buf * (128 * VPB) + r * VPB + c * 16;
            const __nv_bfloat16* g = (arr ? Vtl : Vth) + ho + (size_t)r * NS + n0 + c * 8;
            cpa16(so, g);
        }
    };

    loadKV(0, 0);
    CPA_COMMIT();

    const int rmin = q0 + wid * 16;
    float o[16][4];
#pragma unroll
    for (int nf = 0; nf < 16; ++nf)
#pragma unroll
        for (int e = 0; e < 4; ++e) o[nf][e] = 0.f;
    float m0 = -CUDART_INF_F, m1 = -CUDART_INF_F, l0 = 0.f, l1 = 0.f;

    const uint32_t a_off  = (uint32_t)((wid * 16 + (lane & 15)) * QPB + (lane >> 4) * 16);
    const uint32_t b_row  = (uint32_t)((lane & 7) + ((lane >> 4) << 3));
    const uint32_t b_koff = (uint32_t)(((lane >> 3) & 1) * 16);

    const int niter = q0 / 64 + 2;
    for (int it = 0; it < niter; ++it) {
        const int n0 = it * 64, buf = it & 1;
        if (it + 1 < niter) { loadKV(buf ^ 1, (it + 1) * 64); CPA_COMMIT(); CPA_WAIT1(); }
        else                { CPA_WAIT0(); }
        __syncthreads();

        if (n0 <= rmin + 15) {
            float sc[8][4];
#pragma unroll
            for (int nf = 0; nf < 8; ++nf)
#pragma unroll
                for (int e = 0; e < 4; ++e) sc[nf][e] = 0.f;

            const uint32_t kh_b = sb + OKH + buf * (64 * QPB) + b_row * QPB + b_koff;
            const uint32_t kl_b = sb + OKL + buf * (64 * QPB) + b_row * QPB + b_koff;
#pragma unroll
            for (int t = 0; t < 8; ++t) {
                uint32_t ah[4], av[4];
                ldsm4(ah, sb + OQH + a_off + t * 32);
                ldsm4(av, sb + OQL + a_off + t * 32);
#pragma unroll
                for (int nf2 = 0; nf2 < 4; ++nf2) {
                    uint32_t bh[4], bl[4];
                    ldsm4(bh, kh_b + nf2 * (16 * QPB) + t * 32);
                    ldsm4(bl, kl_b + nf2 * (16 * QPB) + t * 32);
                    mma_bf16(sc[2*nf2],   ah, bh[0], bh[1]);
                    mma_bf16(sc[2*nf2],   ah, bl[0], bl[1]);
                    mma_bf16(sc[2*nf2],   av, bh[0], bh[1]);
                    mma_bf16(sc[2*nf2+1], ah, bh[2], bh[3]);
                    mma_bf16(sc[2*nf2+1], ah, bl[2], bl[3]);
                    mma_bf16(sc[2*nf2+1], av, bh[2], bh[3]);
                }
            }

            const int r_lo = rmin + (lane >> 2);
            if (n0 + 63 > rmin) {
#pragma unroll
                for (int nf = 0; nf < 8; ++nf) {
                    int cbase = n0 + nf * 8 + ((lane & 3) << 1);
#pragma unroll
                    for (int e = 0; e < 4; ++e) {
                        int col = cbase + (e & 1);
                        int row = r_lo + ((e >> 1) << 3);
                        if (col > row) sc[nf][e] = -CUDART_INF_F;
                    }
                }
            }

            float mx0 = -CUDART_INF_F, mx1 = -CUDART_INF_F;
#pragma unroll
            for (int nf = 0; nf < 8; ++nf) {
                mx0 = fmaxf(mx0, fmaxf(sc[nf][0], sc[nf][1]));
                mx1 = fmaxf(mx1, fmaxf(sc[nf][2], sc[nf][3]));
            }
            mx0 = fmaxf(mx0, __shfl_xor_sync(0xffffffffu, mx0, 1));
            mx0 = fmaxf(mx0, __shfl_xor_sync(0xffffffffu, mx0, 2));
            mx1 = fmaxf(mx1, __shfl_xor_sync(0xffffffffu, mx1, 1));
            mx1 = fmaxf(mx1, __shfl_xor_sync(0xffffffffu, mx1, 2));
            float mn0 = fmaxf(m0, mx0), mn1 = fmaxf(m1, mx1);
            float al0 = __expf(m0 - mn0), al1 = __expf(m1 - mn1);
            float rs0 = 0.f, rs1 = 0.f;
#pragma unroll
            for (int nf = 0; nf < 8; ++nf) {
                sc[nf][0] = __expf(sc[nf][0] - mn0);
                sc[nf][1] = __expf(sc[nf][1] - mn0);
                sc[nf][2] = __expf(sc[nf][2] - mn1);
                sc[nf][3] = __expf(sc[nf][3] - mn1);
                rs0 += sc[nf][0] + sc[nf][1];
                rs1 += sc[nf][2] + sc[nf][3];
            }
            rs0 += __shfl_xor_sync(0xffffffffu, rs0, 1);
            rs0 += __shfl_xor_sync(0xffffffffu, rs0, 2);
            rs1 += __shfl_xor_sync(0xffffffffu, rs1, 1);
            rs1 += __shfl_xor_sync(0xffffffffu, rs1, 2);
            l0 = l0 * al0 + rs0;  l1 = l1 * al1 + rs1;
            m0 = mn0;             m1 = mn1;
#pragma unroll
            for (int nf = 0; nf < 16; ++nf) {
                o[nf][0] *= al0; o[nf][1] *= al0;
                o[nf][2] *= al1; o[nf][3] *= al1;
            }

            const uint32_t vh_b = sb + OVH + buf * (128 * VPB) + b_row * VPB + b_koff;
            const uint32_t vl_b = sb + OVL + buf * (128 * VPB) + b_row * VPB + b_koff;
#pragma unroll
            for (int t = 0; t < 4; ++t) {
                uint32_t pah[4], pal[4];
                hilo2(sc[2*t][0],   sc[2*t][1],   pah[0], pal[0]);
                hilo2(sc[2*t][2],   sc[2*t][3],   pah[1], pal[1]);
                hilo2(sc[2*t+1][0], sc[2*t+1][1], pah[2], pal[2]);
                hilo2(sc[2*t+1][2], sc[2*t+1][3], pah[3], pal[3]);
#pragma unroll
                for (int nd2 = 0; nd2 < 8; ++nd2) {
                    uint32_t vh[4], vl[4];
                    ldsm4(vh, vh_b + nd2 * (16 * VPB) + t * 32);
                    ldsm4(vl, vl_b + nd2 * (16 * VPB) + t * 32);
                    mma_bf16(o[2*nd2],   pah, vh[0], vh[1]);
                    mma_bf16(o[2*nd2],   pah, vl[0], vl[1]);
                    mma_bf16(o[2*nd2],   pal, vh[0], vh[1]);
                    mma_bf16(o[2*nd2+1], pah, vh[2], vh[3]);
                    mma_bf16(o[2*nd2+1], pah, vl[2], vl[3]);
                    mma_bf16(o[2*nd2+1], pal, vh[2], vh[3]);
                }
            }
        }
        __syncthreads();
    }

    const float il0 = 1.f / l0, il1 = 1.f / l1;
    const int srow = rmin + (lane >> 2);
    const int dq   = (lane & 3) << 1;
#pragma unroll
    for (int nf = 0; nf < 16; ++nf) {
        int d = nf * 8 + dq;
        size_t base = (size_t)(b * NS) * ND + (size_t)h * DH + d;
        uint32_t hp, lp;
        hilo2(o[nf][0] * il0, o[nf][1] * il0, hp, lp);
        *reinterpret_cast<uint32_t*>(Oh + base + (size_t)srow * ND) = hp;
        *reinterpret_cast<uint32_t*>(Ol + base + (size_t)srow * ND) = lp;
        hilo2(o[nf][2] * il1, o[nf][3] * il1, hp, lp);
        *reinterpret_cast<uint32_t*>(Oh + base + (size_t)(srow + 8) * ND) = hp;
        *reinterpret_cast<uint32_t*>(Ol + base + (size_t)(srow + 8) * ND) = lp;
    }
}

// ---------------------------------------------------------------------------
extern "C" void kernel_launch(void* const* d_in, const int* in_sizes, int n_in,
                              void* d_out, int out_size) {
    const float* x  = (const float*)d_in[0];
    const float* Wq = (const float*)d_in[1];
    const float* Wk = (const float*)d_in[2];
    const float* Wv = (const float*)d_in[3];
    const float* Wo = (const float*)d_in[4];

    __nv_bfloat16 *xh, *xl, *wh, *wl, *qh, *ql, *kh, *kl, *vth, *vtl;
    char *ah8, *al8, *wh8, *wl8;
    float *sa, *ws;
    cudaGetSymbolAddress((void**)&xh,  g_xh);
    cudaGetSymbolAddress((void**)&xl,  g_xl);
    cudaGetSymbolAddress((void**)&wh,  g_wh);
    cudaGetSymbolAddress((void**)&wl,  g_wl);
    cudaGetSymbolAddress((void**)&qh,  g_qh);
    cudaGetSymbolAddress((void**)&ql,  g_ql);
    cudaGetSymbolAddress((void**)&kh,  g_kh);
    cudaGetSymbolAddress((void**)&kl,  g_kl);
    cudaGetSymbolAddress((void**)&vth, g_vth);
    cudaGetSymbolAddress((void**)&vtl, g_vtl);
    cudaGetSymbolAddress((void**)&ah8, g_ah8);
    cudaGetSymbolAddress((void**)&al8, g_al8);
    cudaGetSymbolAddress((void**)&wh8, g_wh8);
    cudaGetSymbolAddress((void**)&wl8, g_wl8);
    cudaGetSymbolAddress((void**)&sa,  g_sa);
    cudaGetSymbolAddress((void**)&ws,  g_ws);

    cudaFuncSetAttribute(gemm_qkv8, cudaFuncAttributeMaxDynamicSharedMemorySize, GSMEM8);
    cudaFuncSetAttribute(gemm_out,  cudaFuncAttributeMaxDynamicSharedMemorySize, GSMEM);
    cudaFuncSetAttribute(flash_mma, cudaFuncAttributeMaxDynamicSharedMemorySize, FSMEM);

    OutPtrs op{qh, ql, kh, kl, vth, vtl};

    // Prep: quantize x rows; weight col scales; transpose+quantize all weights.
    quant_rows<<<NM / 8, 256>>>(x, ah8, al8, sa);
    colmax_w<<<dim3(ND / 256, 3), 256>>>(Wq, Wk, Wv, ws);
    quant_wT4<<<dim3(ND / 32, ND / 32, 4), dim3(32, 8)>>>(
        Wq, Wk, Wv, Wo, wh8, wl8, ws, wh, wl);

    // Merged int8 Q/K/V projections: 3 modes x 32 col-tiles x 32 row-tiles.
    gemm_qkv8<<<dim3(96, NM / 128), 256, GSMEM8>>>(ah8, al8, wh8, wl8, sa, ws, op);

    // Flash attention writes bf16 hi/lo attn-out into xh/xl.
    flash_mma<<<dim3(NS / 128, NH, NB), 256, FSMEM>>>(qh, ql, kh, kl, vth, vtl, xh, xl);

    // Final projection (bf16x3, Wo).
    gemm_out<<<dim3(ND / 128, NM / 128), 256, GSMEM>>>(xh, xl, wh, wl, (float*)d_out);
}

// round 13
// speedup vs baseline: 1.9137x; 1.9137x over previous
#include <cuda_runtime.h>
#include <cuda_bf16.h>
#include <math.h>
#include <math_constants.h>
#include <cstdint>

// Problem constants
#define NB 2
#define NS 2048
#define ND 2048
#define NH 16
#define DH 128
#define NM 4096   // NB*NS

#define L2_10K_OVER_64 0.2076205059304602f   // log2(10000)/64
#define QSCALE 0.08838834764831845f          // 1/sqrt(128)

// Scratch: sanctioned __device__ globals (no runtime allocation).
__device__ __nv_bfloat16 g_xh [NM*ND];         // activation hi (x, then attn-out)
__device__ __nv_bfloat16 g_xl [NM*ND];         // activation lo
__device__ __nv_bfloat16 g_wh [4*ND*ND];       // transposed weights hi [w][n][k]
__device__ __nv_bfloat16 g_wl [4*ND*ND];       // transposed weights lo
__device__ __nv_bfloat16 g_qh [NB*NH*NS*DH];   // Q hi  (B,H,S,D), roped+scaled
__device__ __nv_bfloat16 g_ql [NB*NH*NS*DH];
__device__ __nv_bfloat16 g_kh [NB*NH*NS*DH];   // K hi  (B,H,S,D), roped
__device__ __nv_bfloat16 g_kl [NB*NH*NS*DH];
__device__ __nv_bfloat16 g_vth[NB*NH*DH*NS];   // V^T hi (B,H,D,S)
__device__ __nv_bfloat16 g_vtl[NB*NH*DH*NS];

struct OutPtrs {
    __nv_bfloat16 *qh, *ql, *kh, *kl, *vth, *vtl;
};

// ============================ PTX helpers ==================================
__device__ __forceinline__ uint32_t smem_u32(const void* p) {
    uint32_t a;
    asm("{ .reg .u64 t; cvta.to.shared.u64 t, %1; cvt.u32.u64 %0, t; }"
        : "=r"(a) : "l"(p));
    return a;
}

__device__ __forceinline__ void ldsm4(uint32_t* r, uint32_t addr) {
    asm volatile("ldmatrix.sync.aligned.m8n8.x4.shared.b16 {%0,%1,%2,%3}, [%4];"
        : "=r"(r[0]), "=r"(r[1]), "=r"(r[2]), "=r"(r[3]) : "r"(addr));
}

__device__ __forceinline__ void mma_bf16(float* c, const uint32_t* a,
                                         uint32_t b0, uint32_t b1) {
    asm volatile(
        "mma.sync.aligned.m16n8k16.row.col.f32.bf16.bf16.f32 "
        "{%0,%1,%2,%3}, {%4,%5,%6,%7}, {%8,%9}, {%0,%1,%2,%3};"
        : "+f"(c[0]), "+f"(c[1]), "+f"(c[2]), "+f"(c[3])
        : "r"(a[0]), "r"(a[1]), "r"(a[2]), "r"(a[3]), "r"(b0), "r"(b1));
}

__device__ __forceinline__ void cpa16(uint32_t saddr, const void* gaddr) {
    asm volatile("cp.async.cg.shared.global [%0], [%1], 16;"
                 :: "r"(saddr), "l"(gaddr));
}
#define CPA_COMMIT() asm volatile("cp.async.commit_group;")
#define CPA_WAIT1()  asm volatile("cp.async.wait_group 1;")
#define CPA_WAIT0()  asm volatile("cp.async.wait_group 0;")

// pack (a,b) into bf16x2 hi word + bf16x2 lo-residual word
__device__ __forceinline__ void hilo2(float a, float b, uint32_t& hi, uint32_t& lo) {
    __nv_bfloat16 ha = __float2bfloat16_rn(a);
    __nv_bfloat16 hb = __float2bfloat16_rn(b);
    __nv_bfloat162 hp(ha, hb);
    __nv_bfloat162 lp = __floats2bfloat162_rn(a - __bfloat162float(ha),
                                              b - __bfloat162float(hb));
    hi = *reinterpret_cast<uint32_t*>(&hp);
    lo = *reinterpret_cast<uint32_t*>(&lp);
}

// =========================== split kernels =================================
__global__ void __launch_bounds__(256) split_act(const float* __restrict__ in,
                                                 __nv_bfloat16* __restrict__ hi,
                                                 __nv_bfloat16* __restrict__ lo) {
    int i = (blockIdx.x * 256 + threadIdx.x) * 4;
    float4 v = *(const float4*)(in + i);
    uint32_t h0, l0, h1, l1;
    hilo2(v.x, v.y, h0, l0);
    hilo2(v.z, v.w, h1, l1);
    *(uint2*)(hi + i) = make_uint2(h0, h1);
    *(uint2*)(lo + i) = make_uint2(l0, l1);
}

// All four W[k][n] fp32 -> Wt hi/lo bf16 [w][n][k] in ONE launch (grid.z = w)
__global__ void __launch_bounds__(256) split_wT4(
    const float* __restrict__ W0, const float* __restrict__ W1,
    const float* __restrict__ W2, const float* __restrict__ W3,
    __nv_bfloat16* __restrict__ th, __nv_bfloat16* __restrict__ tl) {
    __shared__ float t[32][33];
    const int w  = blockIdx.z;
    const float* W = (w == 0) ? W0 : (w == 1) ? W1 : (w == 2) ? W2 : W3;
    const size_t wo = (size_t)w * ND * ND;
    const int bx = blockIdx.x * 32;   // n tile
    const int by = blockIdx.y * 32;   // k tile
    const int tx = threadIdx.x, ty = threadIdx.y;
#pragma unroll
    for (int j = ty; j < 32; j += 8)
        t[j][tx] = W[(size_t)(by + j) * ND + bx + tx];
    __syncthreads();
#pragma unroll
    for (int j = ty; j < 32; j += 8) {
        float v = t[tx][j];           // = W[by+tx][bx+j]
        __nv_bfloat16 h = __float2bfloat16_rn(v);
        __nv_bfloat16 l = __float2bfloat16_rn(v - __bfloat162float(h));
        th[wo + (size_t)(bx + j) * ND + by + tx] = h;
        tl[wo + (size_t)(bx + j) * ND + by + tx] = l;
    }
}

// ===================== HMMA bf16x3 GEMM mainloop ===========================
#define APITCH 80
#define TILE_BYTES (128 * APITCH)
#define STAGE_BYTES (4 * TILE_BYTES)
#define GSMEM (2 * STAGE_BYTES)            // 81920

// Arow/Brow pre-offset to the CTA tile's first row; row stride ND.
__device__ __forceinline__ void mma_mainloop(
    float acc[2][8][4],
    const __nv_bfloat16* __restrict__ ArowH, const __nv_bfloat16* __restrict__ ArowL,
    const __nv_bfloat16* __restrict__ BrowH, const __nv_bfloat16* __restrict__ BrowL,
    uint32_t sbase, int tid, int wm, int wn, int lane)
{
    auto load_stage = [&](int buf, int k0) {
#pragma unroll
        for (int t = 0; t < 8; ++t) {
            int id   = tid + t * 256;
            int tile = id >> 9;
            int rem  = id & 511;
            int r    = rem >> 2;
            int c    = rem & 3;
            uint32_t so = sbase + buf * STAGE_BYTES + tile * TILE_BYTES
                        + r * APITCH + c * 16;
            const __nv_bfloat16* g;
            if      (tile == 0) g = ArowH + (size_t)r * ND + k0 + c * 8;
            else if (tile == 1) g = ArowL + (size_t)r * ND + k0 + c * 8;
            else if (tile == 2) g = BrowH + (size_t)r * ND + k0 + c * 8;
            else                g = BrowL + (size_t)r * ND + k0 + c * 8;
            cpa16(so, g);
        }
        CPA_COMMIT();
    };

    load_stage(0, 0);

    for (int it = 0; it < 64; ++it) {
        const int buf = it & 1;
        if (it + 1 < 64) { load_stage(buf ^ 1, (it + 1) * 32); CPA_WAIT1(); }
        else             { CPA_WAIT0(); }
        __syncthreads();

        const uint32_t sA  = sbase + buf * STAGE_BYTES;
        const uint32_t sAl = sA + TILE_BYTES;
        const uint32_t sB  = sA + 2 * TILE_BYTES;
        const uint32_t sBl = sA + 3 * TILE_BYTES;

#pragma unroll
        for (int ks = 0; ks < 2; ++ks) {
            const int akb = ks * 32 + (lane >> 4) * 16;
            uint32_t ah[2][4], al[2][4];
#pragma unroll
            for (int mf = 0; mf < 2; ++mf) {
                uint32_t ro = (wm * 32 + mf * 16 + (lane & 15)) * APITCH + akb;
                ldsm4(ah[mf], sA  + ro);
                ldsm4(al[mf], sAl + ro);
            }
            const int brow = wn * 64 + (lane & 7) + ((lane >> 4) << 3);
            const int bkb  = ks * 32 + ((lane >> 3) & 1) * 16;
#pragma unroll
            for (int nf2 = 0; nf2 < 4; ++nf2) {
                uint32_t bo = (brow + nf2 * 16) * APITCH + bkb;
                uint32_t bh[4], bl[4];
                ldsm4(bh, sB  + bo);
                ldsm4(bl, sBl + bo);
#pragma unroll
                for (int half = 0; half < 2; ++half) {
                    uint32_t h0 = bh[half * 2], h1 = bh[half * 2 + 1];
                    uint32_t l0 = bl[half * 2], l1 = bl[half * 2 + 1];
                    int nf = nf2 * 2 + half;
#pragma unroll
                    for (int mf = 0; mf < 2; ++mf) {
                        mma_bf16(acc[mf][nf], ah[mf], h0, h1);
                        mma_bf16(acc[mf][nf], ah[mf], l0, l1);
                        mma_bf16(acc[mf][nf], al[mf], h0, h1);
                    }
                }
            }
        }
        __syncthreads();
    }
}

// ---- merged Q/K/V projections: grid.x = 48 (mode = blockIdx.x >> 4) ----
__global__ void __launch_bounds__(256, 2) gemm_qkv(
    const __nv_bfloat16* __restrict__ Ah, const __nv_bfloat16* __restrict__ Al,
    const __nv_bfloat16* __restrict__ Wh, const __nv_bfloat16* __restrict__ Wl,
    OutPtrs op)
{
    extern __shared__ char smc[];
    const uint32_t sbase = smem_u32(smc);
    const int tid  = threadIdx.x;
    const int wid  = tid >> 5;
    const int lane = tid & 31;
    const int wm   = wid & 3;
    const int wn   = wid >> 2;
    const int mode = blockIdx.x >> 4;              // 0=Q 1=K 2=V
    const int col0 = (blockIdx.x & 15) * 128;
    const int row0 = blockIdx.y * 128;
    const size_t wo = (size_t)mode * ND * ND;

    float acc[2][8][4];
#pragma unroll
    for (int mf = 0; mf < 2; ++mf)
#pragma unroll
        for (int nf = 0; nf < 8; ++nf)
#pragma unroll
            for (int e = 0; e < 4; ++e) acc[mf][nf][e] = 0.f;

    mma_mainloop(acc, Ah + (size_t)row0 * ND, Al + (size_t)row0 * ND,
                 Wh + wo + (size_t)col0 * ND, Wl + wo + (size_t)col0 * ND,
                 sbase, tid, wm, wn, lane);

    __nv_bfloat16* Ch = (mode == 0) ? op.qh : (mode == 1) ? op.kh : op.vth;
    __nv_bfloat16* Cl = (mode == 0) ? op.ql : (mode == 1) ? op.kl : op.vtl;

#pragma unroll
    for (int mf = 0; mf < 2; ++mf) {
        const int mrow = row0 + wm * 32 + mf * 16 + (lane >> 2);
#pragma unroll
        for (int rr = 0; rr < 2; ++rr) {
            const int m  = mrow + rr * 8;
            const int bb = m >> 11, ss = m & 2047;
#pragma unroll
            for (int nf = 0; nf < 8; ++nf) {
                const int cloc = wn * 64 + nf * 8 + ((lane & 3) << 1);
                const int col  = col0 + cloc;
                const int h    = col >> 7;
                const int d    = cloc & 127;
                float v0 = acc[mf][nf][rr * 2 + 0];
                float v1 = acc[mf][nf][rr * 2 + 1];
                if (mode == 2) {
                    size_t vb = ((size_t)(bb * NH + h) * DH + d) * NS + ss;
                    __nv_bfloat16 h0 = __float2bfloat16_rn(v0);
                    __nv_bfloat16 h1 = __float2bfloat16_rn(v1);
                    Ch[vb]      = h0;
                    Ch[vb + NS] = h1;
                    Cl[vb]      = __float2bfloat16_rn(v0 - __bfloat162float(h0));
                    Cl[vb + NS] = __float2bfloat16_rn(v1 - __bfloat162float(h1));
                } else {
                    size_t ob = (((size_t)(bb * NH + h) * NS + ss) << 7) + d;
                    float pos  = (float)ss;
                    float inv0 = exp2f(-(float)( d      & 63) * L2_10K_OVER_64);
                    float inv1 = exp2f(-(float)((d + 1) & 63) * L2_10K_OVER_64);
                    float s0, c0, s1, c1;
                    sincosf(pos * inv0, &s0, &c0);
                    sincosf(pos * inv1, &s1, &c1);
                    float o0 = v0 * c0 - v1 * s0;
                    float o1 = v1 * c1 + v0 * s1;
                    if (mode == 0) { o0 *= QSCALE; o1 *= QSCALE; }
                    uint32_t hp, lp;
                    hilo2(o0, o1, hp, lp);
                    *reinterpret_cast<uint32_t*>(Ch + ob) = hp;
                    *reinterpret_cast<uint32_t*>(Cl + ob) = lp;
                }
            }
        }
    }
}

// ---- final projection: fp32 row-major out ----
__global__ void __launch_bounds__(256, 2) gemm_out(
    const __nv_bfloat16* __restrict__ Ah, const __nv_bfloat16* __restrict__ Al,
    const __nv_bfloat16* __restrict__ Wh, const __nv_bfloat16* __restrict__ Wl,
    float* __restrict__ C)
{
    extern __shared__ char smc[];
    const uint32_t sbase = smem_u32(smc);
    const int tid  = threadIdx.x;
    const int wid  = tid >> 5;
    const int lane = tid & 31;
    const int wm   = wid & 3;
    const int wn   = wid >> 2;
    const int col0 = blockIdx.x * 128;
    const int row0 = blockIdx.y * 128;

    float acc[2][8][4];
#pragma unroll
    for (int mf = 0; mf < 2; ++mf)
#pragma unroll
        for (int nf = 0; nf < 8; ++nf)
#pragma unroll
            for (int e = 0; e < 4; ++e) acc[mf][nf][e] = 0.f;

    mma_mainloop(acc, Ah + (size_t)row0 * ND, Al + (size_t)row0 * ND,
                 Wh + (size_t)col0 * ND, Wl + (size_t)col0 * ND,
                 sbase, tid, wm, wn, lane);

#pragma unroll
    for (int mf = 0; mf < 2; ++mf) {
        const int mrow = row0 + wm * 32 + mf * 16 + (lane >> 2);
#pragma unroll
        for (int rr = 0; rr < 2; ++rr) {
            const int m = mrow + rr * 8;
#pragma unroll
            for (int nf = 0; nf < 8; ++nf) {
                const int col = col0 + wn * 64 + nf * 8 + ((lane & 3) << 1);
                *(float2*)(C + (size_t)m * ND + col) =
                    make_float2(acc[mf][nf][rr * 2 + 0], acc[mf][nf][rr * 2 + 1]);
            }
        }
    }
}

// ======================= flash attention (mma.sync) ========================
// Paired q-tiles per CTA for load balance: CTA bx handles qt = NQT-1-bx
// (heavy) then qt = bx (light) -> uniform work, grid 256 CTAs.
#define NQT (NS / 128)                // 16
#define QPB 272
#define VPB 144
#define OQH 0
#define OQL (OQH + 128*QPB)
#define OKH (OQL + 128*QPB)
#define OKL (OKH + 2*64*QPB)
#define OVH (OKL + 2*64*QPB)
#define OVL (OVH + 2*128*VPB)
#define FSMEM (OVL + 2*128*VPB)       // 212992

__global__ void __launch_bounds__(256, 1) flash_mma(
    const __nv_bfloat16* __restrict__ Qh, const __nv_bfloat16* __restrict__ Ql,
    const __nv_bfloat16* __restrict__ Kh, const __nv_bfloat16* __restrict__ Kl,
    const __nv_bfloat16* __restrict__ Vth, const __nv_bfloat16* __restrict__ Vtl,
    __nv_bfloat16* __restrict__ Oh, __nv_bfloat16* __restrict__ Ol)
{
    extern __shared__ char smc[];
    const uint32_t sb = smem_u32(smc);
    const int tid = threadIdx.x, wid = tid >> 5, lane = tid & 31;
    const int h  = blockIdx.y, b = blockIdx.z;
    const size_t ho = (size_t)(b * NH + h) * NS * DH;

    const uint32_t a_off  = (uint32_t)((wid * 16 + (lane & 15)) * QPB + (lane >> 4) * 16);
    const uint32_t b_row  = (uint32_t)((lane & 7) + ((lane >> 4) << 3));
    const uint32_t b_koff = (uint32_t)(((lane >> 3) & 1) * 16);

    auto loadKV = [&](int buf, int n0) {
#pragma unroll
        for (int t = 0; t < 8; ++t) {
            int id  = tid + t * 256;
            int arr = id >> 10;
            int rem = id & 1023;
            int r = rem >> 4, c = rem & 15;
            uint32_t so = sb + (arr ? OKL : OKH) + buf * (64 * QPB) + r * QPB + c * 16;
            const __nv_bfloat16* g = (arr ? Kl : Kh) + ho + (size_t)(n0 + r) * DH + c * 8;
            cpa16(so, g);
        }
#pragma unroll
        for (int t = 0; t < 8; ++t) {
            int id  = tid + t * 256;
            int arr = id >> 10;
            int rem = id & 1023;
            int r = rem >> 3, c = rem & 7;
            uint32_t so = sb + (arr ? OVL : OVH) + buf * (128 * VPB) + r * VPB + c * 16;
            const __nv_bfloat16* g = (arr ? Vtl : Vth) + ho + (size_t)r * NS + n0 + c * 8;
            cpa16(so, g);
        }
    };

#pragma unroll 1
    for (int rep = 0; rep < 2; ++rep) {
        const int qt = rep == 0 ? (NQT - 1 - (int)blockIdx.x) : (int)blockIdx.x;
        const int q0 = qt * 128;

        // Q tile for this rep (smem safe: all warps passed the last k-iter sync)
#pragma unroll
        for (int t = 0; t < 16; ++t) {
            int id  = tid + t * 256;
            int arr = id >> 11;
            int rem = id & 2047;
            int r = rem >> 4, c = rem & 15;
            uint32_t so = sb + (arr ? OQL : OQH) + r * QPB + c * 16;
            const __nv_bfloat16* g = (arr ? Ql : Qh) + ho + (size_t)(q0 + r) * DH + c * 8;
            cpa16(so, g);
        }
        loadKV(0, 0);
        CPA_COMMIT();

        const int rmin = q0 + wid * 16;
        float o[16][4];
#pragma unroll
        for (int nf = 0; nf < 16; ++nf)
#pragma unroll
            for (int e = 0; e < 4; ++e) o[nf][e] = 0.f;
        float m0 = -CUDART_INF_F, m1 = -CUDART_INF_F, l0 = 0.f, l1 = 0.f;

        const int niter = q0 / 64 + 2;
        for (int it = 0; it < niter; ++it) {
            const int n0 = it * 64, buf = it & 1;
            if (it + 1 < niter) { loadKV(buf ^ 1, (it + 1) * 64); CPA_COMMIT(); CPA_WAIT1(); }
            else                { CPA_WAIT0(); }
            __syncthreads();

            if (n0 <= rmin + 15) {
                float sc[8][4];
#pragma unroll
                for (int nf = 0; nf < 8; ++nf)
#pragma unroll
                    for (int e = 0; e < 4; ++e) sc[nf][e] = 0.f;

                const uint32_t kh_b = sb + OKH + buf * (64 * QPB) + b_row * QPB + b_koff;
                const uint32_t kl_b = sb + OKL + buf * (64 * QPB) + b_row * QPB + b_koff;
#pragma unroll
                for (int t = 0; t < 8; ++t) {
                    uint32_t ah[4], av[4];
                    ldsm4(ah, sb + OQH + a_off + t * 32);
                    ldsm4(av, sb + OQL + a_off + t * 32);
#pragma unroll
                    for (int nf2 = 0; nf2 < 4; ++nf2) {
                        uint32_t bh[4], bl[4];
                        ldsm4(bh, kh_b + nf2 * (16 * QPB) + t * 32);
                        ldsm4(bl, kl_b + nf2 * (16 * QPB) + t * 32);
                        mma_bf16(sc[2*nf2],   ah, bh[0], bh[1]);
                        mma_bf16(sc[2*nf2],   ah, bl[0], bl[1]);
                        mma_bf16(sc[2*nf2],   av, bh[0], bh[1]);
                        mma_bf16(sc[2*nf2+1], ah, bh[2], bh[3]);
                        mma_bf16(sc[2*nf2+1], ah, bl[2], bl[3]);
                        mma_bf16(sc[2*nf2+1], av, bh[2], bh[3]);
                    }
                }

                const int r_lo = rmin + (lane >> 2);
                if (n0 + 63 > rmin) {
#pragma unroll
                    for (int nf = 0; nf < 8; ++nf) {
                        int cbase = n0 + nf * 8 + ((lane & 3) << 1);
#pragma unroll
                        for (int e = 0; e < 4; ++e) {
                            int col = cbase + (e & 1);
                            int row = r_lo + ((e >> 1) << 3);
                            if (col > row) sc[nf][e] = -CUDART_INF_F;
                        }
                    }
                }

                float mx0 = -CUDART_INF_F, mx1 = -CUDART_INF_F;
#pragma unroll
                for (int nf = 0; nf < 8; ++nf) {
                    mx0 = fmaxf(mx0, fmaxf(sc[nf][0], sc[nf][1]));
                    mx1 = fmaxf(mx1, fmaxf(sc[nf][2], sc[nf][3]));
                }
                mx0 = fmaxf(mx0, __shfl_xor_sync(0xffffffffu, mx0, 1));
                mx0 = fmaxf(mx0, __shfl_xor_sync(0xffffffffu, mx0, 2));
                mx1 = fmaxf(mx1, __shfl_xor_sync(0xffffffffu, mx1, 1));
                mx1 = fmaxf(mx1, __shfl_xor_sync(0xffffffffu, mx1, 2));
                float mn0 = fmaxf(m0, mx0), mn1 = fmaxf(m1, mx1);
                float al0 = __expf(m0 - mn0), al1 = __expf(m1 - mn1);
                float rs0 = 0.f, rs1 = 0.f;
#pragma unroll
                for (int nf = 0; nf < 8; ++nf) {
                    sc[nf][0] = __expf(sc[nf][0] - mn0);
                    sc[nf][1] = __expf(sc[nf][1] - mn0);
                    sc[nf][2] = __expf(sc[nf][2] - mn1);
                    sc[nf][3] = __expf(sc[nf][3] - mn1);
                    rs0 += sc[nf][0] + sc[nf][1];
                    rs1 += sc[nf][2] + sc[nf][3];
                }
                rs0 += __shfl_xor_sync(0xffffffffu, rs0, 1);
                rs0 += __shfl_xor_sync(0xffffffffu, rs0, 2);
                rs1 += __shfl_xor_sync(0xffffffffu, rs1, 1);
                rs1 += __shfl_xor_sync(0xffffffffu, rs1, 2);
                l0 = l0 * al0 + rs0;  l1 = l1 * al1 + rs1;
                m0 = mn0;             m1 = mn1;
#pragma unroll
                for (int nf = 0; nf < 16; ++nf) {
                    o[nf][0] *= al0; o[nf][1] *= al0;
                    o[nf][2] *= al1; o[nf][3] *= al1;
                }

                const uint32_t vh_b = sb + OVH + buf * (128 * VPB) + b_row * VPB + b_koff;
                const uint32_t vl_b = sb + OVL + buf * (128 * VPB) + b_row * VPB + b_koff;
#pragma unroll
                for (int t = 0; t < 4; ++t) {
                    uint32_t pah[4], pal[4];
                    hilo2(sc[2*t][0],   sc[2*t][1],   pah[0], pal[0]);
                    hilo2(sc[2*t][2],   sc[2*t][3],   pah[1], pal[1]);
                    hilo2(sc[2*t+1][0], sc[2*t+1][1], pah[2], pal[2]);
                    hilo2(sc[2*t+1][2], sc[2*t+1][3], pah[3], pal[3]);
#pragma unroll
                    for (int nd2 = 0; nd2 < 8; ++nd2) {
                        uint32_t vh[4], vl[4];
                        ldsm4(vh, vh_b + nd2 * (16 * VPB) + t * 32);
                        ldsm4(vl, vl_b + nd2 * (16 * VPB) + t * 32);
                        mma_bf16(o[2*nd2],   pah, vh[0], vh[1]);
                        mma_bf16(o[2*nd2],   pah, vl[0], vl[1]);
                        mma_bf16(o[2*nd2],   pal, vh[0], vh[1]);
                        mma_bf16(o[2*nd2+1], pah, vh[2], vh[3]);
                        mma_bf16(o[2*nd2+1], pah, vl[2], vl[3]);
                        mma_bf16(o[2*nd2+1], pal, vh[2], vh[3]);
                    }
                }
            }
            __syncthreads();
        }

        const float il0 = 1.f / l0, il1 = 1.f / l1;
        const int srow = rmin + (lane >> 2);
        const int dq   = (lane & 3) << 1;
#pragma unroll
        for (int nf = 0; nf < 16; ++nf) {
            int d = nf * 8 + dq;
            size_t base = (size_t)(b * NS) * ND + (size_t)h * DH + d;
            uint32_t hp, lp;
            hilo2(o[nf][0] * il0, o[nf][1] * il0, hp, lp);
            *reinterpret_cast<uint32_t*>(Oh + base + (size_t)srow * ND) = hp;
            *reinterpret_cast<uint32_t*>(Ol + base + (size_t)srow * ND) = lp;
            hilo2(o[nf][2] * il1, o[nf][3] * il1, hp, lp);
            *reinterpret_cast<uint32_t*>(Oh + base + (size_t)(srow + 8) * ND) = hp;
            *reinterpret_cast<uint32_t*>(Ol + base + (size_t)(srow + 8) * ND) = lp;
        }
    }
}

// ---------------------------------------------------------------------------
extern "C" void kernel_launch(void* const* d_in, const int* in_sizes, int n_in,
                              void* d_out, int out_size) {
    const float* x  = (const float*)d_in[0];
    const float* Wq = (const float*)d_in[1];
    const float* Wk = (const float*)d_in[2];
    const float* Wv = (const float*)d_in[3];
    const float* Wo = (const float*)d_in[4];

    __nv_bfloat16 *xh, *xl, *wh, *wl, *qh, *ql, *kh, *kl, *vth, *vtl;
    cudaGetSymbolAddress((void**)&xh,  g_xh);
    cudaGetSymbolAddress((void**)&xl,  g_xl);
    cudaGetSymbolAddress((void**)&wh,  g_wh);
    cudaGetSymbolAddress((void**)&wl,  g_wl);
    cudaGetSymbolAddress((void**)&qh,  g_qh);
    cudaGetSymbolAddress((void**)&ql,  g_ql);
    cudaGetSymbolAddress((void**)&kh,  g_kh);
    cudaGetSymbolAddress((void**)&kl,  g_kl);
    cudaGetSymbolAddress((void**)&vth, g_vth);
    cudaGetSymbolAddress((void**)&vtl, g_vtl);

    cudaFuncSetAttribute(gemm_qkv, cudaFuncAttributeMaxDynamicSharedMemorySize, GSMEM);
    cudaFuncSetAttribute(gemm_out, cudaFuncAttributeMaxDynamicSharedMemorySize, GSMEM);
    cudaFuncSetAttribute(flash_mma, cudaFuncAttributeMaxDynamicSharedMemorySize, FSMEM);

    OutPtrs op{qh, ql, kh, kl, vth, vtl};

    const int actblocks = NM * ND / (256 * 4);

    // Independent prep: activation split + all four weight transpose-splits.
    split_act<<<actblocks, 256>>>(x, xh, xl);
    split_wT4<<<dim3(ND / 32, ND / 32, 4), dim3(32, 8)>>>(Wq, Wk, Wv, Wo, wh, wl);

    // Merged Q/K/V projections (one launch, 1536 CTAs).
    gemm_qkv<<<dim3(48, NM / 128), 256, GSMEM>>>(xh, xl, wh, wl, op);

    // Flash attention: paired q-tiles, 256 CTAs; writes bf16 hi/lo into xh/xl.
    flash_mma<<<dim3(NQT / 2, NH, NB), 256, FSMEM>>>(qh, ql, kh, kl, vth, vtl, xh, xl);

    // Final projection (weight index 3).
    gemm_out<<<dim3(ND / 128, NM / 128), 256, GSMEM>>>(
        xh, xl, wh + (size_t)3 * ND * ND, wl + (size_t)3 * ND * ND, (float*)d_out);
}

// round 14
// speedup vs baseline: 1.9248x; 1.0058x over previous
#include <cuda_runtime.h>
#include <cuda_bf16.h>
#include <math.h>
#include <math_constants.h>
#include <cstdint>

// Problem constants
#define NB 2
#define NS 2048
#define ND 2048
#define NH 16
#define DH 128
#define NM 4096   // NB*NS

#define L2_10K_OVER_64 0.2076205059304602f   // log2(10000)/64
#define QSCALE 0.08838834764831845f          // 1/sqrt(128)

// Scratch: sanctioned __device__ globals (no runtime allocation).
__device__ __nv_bfloat16 g_xh [NM*ND];         // activation hi (x, then attn-out)
__device__ __nv_bfloat16 g_xl [NM*ND];         // activation lo
__device__ __nv_bfloat16 g_wh [4*ND*ND];       // transposed weights hi [w][n][k]
__device__ __nv_bfloat16 g_wl [4*ND*ND];       // transposed weights lo
__device__ __nv_bfloat16 g_qh [NB*NH*NS*DH];   // Q hi  (B,H,S,D), roped+scaled
__device__ __nv_bfloat16 g_ql [NB*NH*NS*DH];
__device__ __nv_bfloat16 g_kh [NB*NH*NS*DH];   // K hi  (B,H,S,D), roped
__device__ __nv_bfloat16 g_kl [NB*NH*NS*DH];
__device__ __nv_bfloat16 g_vth[NB*NH*DH*NS];   // V^T hi (B,H,D,S)
__device__ __nv_bfloat16 g_vtl[NB*NH*DH*NS];
__device__ float2 g_rope[NS*64];               // (cos,sin) per (s, freq-index)

struct OutPtrs {
    __nv_bfloat16 *qh, *ql, *kh, *kl, *vth, *vtl;
};

// ============================ PTX helpers ==================================
__device__ __forceinline__ uint32_t smem_u32(const void* p) {
    uint32_t a;
    asm("{ .reg .u64 t; cvta.to.shared.u64 t, %1; cvt.u32.u64 %0, t; }"
        : "=r"(a) : "l"(p));
    return a;
}

__device__ __forceinline__ void ldsm4(uint32_t* r, uint32_t addr) {
    asm volatile("ldmatrix.sync.aligned.m8n8.x4.shared.b16 {%0,%1,%2,%3}, [%4];"
        : "=r"(r[0]), "=r"(r[1]), "=r"(r[2]), "=r"(r[3]) : "r"(addr));
}

__device__ __forceinline__ void mma_bf16(float* c, const uint32_t* a,
                                         uint32_t b0, uint32_t b1) {
    asm volatile(
        "mma.sync.aligned.m16n8k16.row.col.f32.bf16.bf16.f32 "
        "{%0,%1,%2,%3}, {%4,%5,%6,%7}, {%8,%9}, {%0,%1,%2,%3};"
        : "+f"(c[0]), "+f"(c[1]), "+f"(c[2]), "+f"(c[3])
        : "r"(a[0]), "r"(a[1]), "r"(a[2]), "r"(a[3]), "r"(b0), "r"(b1));
}

__device__ __forceinline__ void cpa16(uint32_t saddr, const void* gaddr) {
    asm volatile("cp.async.cg.shared.global [%0], [%1], 16;"
                 :: "r"(saddr), "l"(gaddr));
}
#define CPA_COMMIT() asm volatile("cp.async.commit_group;")
#define CPA_WAIT1()  asm volatile("cp.async.wait_group 1;")
#define CPA_WAIT0()  asm volatile("cp.async.wait_group 0;")

// pack (a,b) into bf16x2 hi word + bf16x2 lo-residual word
__device__ __forceinline__ void hilo2(float a, float b, uint32_t& hi, uint32_t& lo) {
    __nv_bfloat16 ha = __float2bfloat16_rn(a);
    __nv_bfloat16 hb = __float2bfloat16_rn(b);
    __nv_bfloat162 hp(ha, hb);
    __nv_bfloat162 lp = __floats2bfloat162_rn(a - __bfloat162float(ha),
                                              b - __bfloat162float(hb));
    hi = *reinterpret_cast<uint32_t*>(&hp);
    lo = *reinterpret_cast<uint32_t*>(&lp);
}

// =========================== prep kernels ==================================
__global__ void __launch_bounds__(256) split_act(const float* __restrict__ in,
                                                 __nv_bfloat16* __restrict__ hi,
                                                 __nv_bfloat16* __restrict__ lo) {
    int i = (blockIdx.x * 256 + threadIdx.x) * 4;
    float4 v = *(const float4*)(in + i);
    uint32_t h0, l0, h1, l1;
    hilo2(v.x, v.y, h0, l0);
    hilo2(v.z, v.w, h1, l1);
    *(uint2*)(hi + i) = make_uint2(h0, h1);
    *(uint2*)(lo + i) = make_uint2(l0, l1);
}

// RoPE table: exactly the same FP formula the epilogue used inline.
__global__ void __launch_bounds__(256) rope_table(float2* __restrict__ tab) {
    int idx = blockIdx.x * 256 + threadIdx.x;     // 0 .. NS*64-1
    int ss  = idx >> 6;
    int i   = idx & 63;
    float inv = exp2f(-(float)i * L2_10K_OVER_64);
    float s, c;
    sincosf((float)ss * inv, &s, &c);
    tab[idx] = make_float2(c, s);
}

// All four W[k][n] fp32 -> Wt hi/lo bf16 [w][n][k] in ONE launch (grid.z = w)
__global__ void __launch_bounds__(256) split_wT4(
    const float* __restrict__ W0, const float* __restrict__ W1,
    const float* __restrict__ W2, const float* __restrict__ W3,
    __nv_bfloat16* __restrict__ th, __nv_bfloat16* __restrict__ tl) {
    __shared__ float t[32][33];
    const int w  = blockIdx.z;
    const float* W = (w == 0) ? W0 : (w == 1) ? W1 : (w == 2) ? W2 : W3;
    const size_t wo = (size_t)w * ND * ND;
    const int bx = blockIdx.x * 32;   // n tile
    const int by = blockIdx.y * 32;   // k tile
    const int tx = threadIdx.x, ty = threadIdx.y;
#pragma unroll
    for (int j = ty; j < 32; j += 8)
        t[j][tx] = W[(size_t)(by + j) * ND + bx + tx];
    __syncthreads();
#pragma unroll
    for (int j = ty; j < 32; j += 8) {
        float v = t[tx][j];           // = W[by+tx][bx+j]
        __nv_bfloat16 h = __float2bfloat16_rn(v);
        __nv_bfloat16 l = __float2bfloat16_rn(v - __bfloat162float(h));
        th[wo + (size_t)(bx + j) * ND + by + tx] = h;
        tl[wo + (size_t)(bx + j) * ND + by + tx] = l;
    }
}

// ===================== HMMA bf16x3 GEMM mainloop ===========================
#define APITCH 80
#define TILE_BYTES (128 * APITCH)
#define STAGE_BYTES (4 * TILE_BYTES)
#define GSMEM (2 * STAGE_BYTES)            // 81920

// Arow/Brow pre-offset to the CTA tile's first row; row stride ND.
__device__ __forceinline__ void mma_mainloop(
    float acc[2][8][4],
    const __nv_bfloat16* __restrict__ ArowH, const __nv_bfloat16* __restrict__ ArowL,
    const __nv_bfloat16* __restrict__ BrowH, const __nv_bfloat16* __restrict__ BrowL,
    uint32_t sbase, int tid, int wm, int wn, int lane)
{
    auto load_stage = [&](int buf, int k0) {
#pragma unroll
        for (int t = 0; t < 8; ++t) {
            int id   = tid + t * 256;
            int tile = id >> 9;
            int rem  = id & 511;
            int r    = rem >> 2;
            int c    = rem & 3;
            uint32_t so = sbase + buf * STAGE_BYTES + tile * TILE_BYTES
                        + r * APITCH + c * 16;
            const __nv_bfloat16* g;
            if      (tile == 0) g = ArowH + (size_t)r * ND + k0 + c * 8;
            else if (tile == 1) g = ArowL + (size_t)r * ND + k0 + c * 8;
            else if (tile == 2) g = BrowH + (size_t)r * ND + k0 + c * 8;
            else                g = BrowL + (size_t)r * ND + k0 + c * 8;
            cpa16(so, g);
        }
        CPA_COMMIT();
    };

    load_stage(0, 0);

    for (int it = 0; it < 64; ++it) {
        const int buf = it & 1;
        if (it + 1 < 64) { load_stage(buf ^ 1, (it + 1) * 32); CPA_WAIT1(); }
        else             { CPA_WAIT0(); }
        __syncthreads();

        const uint32_t sA  = sbase + buf * STAGE_BYTES;
        const uint32_t sAl = sA + TILE_BYTES;
        const uint32_t sB  = sA + 2 * TILE_BYTES;
        const uint32_t sBl = sA + 3 * TILE_BYTES;

#pragma unroll
        for (int ks = 0; ks < 2; ++ks) {
            const int akb = ks * 32 + (lane >> 4) * 16;
            uint32_t ah[2][4], al[2][4];
#pragma unroll
            for (int mf = 0; mf < 2; ++mf) {
                uint32_t ro = (wm * 32 + mf * 16 + (lane & 15)) * APITCH + akb;
                ldsm4(ah[mf], sA  + ro);
                ldsm4(al[mf], sAl + ro);
            }
            const int brow = wn * 64 + (lane & 7) + ((lane >> 4) << 3);
            const int bkb  = ks * 32 + ((lane >> 3) & 1) * 16;
#pragma unroll
            for (int nf2 = 0; nf2 < 4; ++nf2) {
                uint32_t bo = (brow + nf2 * 16) * APITCH + bkb;
                uint32_t bh[4], bl[4];
                ldsm4(bh, sB  + bo);
                ldsm4(bl, sBl + bo);
#pragma unroll
                for (int half = 0; half < 2; ++half) {
                    uint32_t h0 = bh[half * 2], h1 = bh[half * 2 + 1];
                    uint32_t l0 = bl[half * 2], l1 = bl[half * 2 + 1];
                    int nf = nf2 * 2 + half;
#pragma unroll
                    for (int mf = 0; mf < 2; ++mf) {
                        mma_bf16(acc[mf][nf], ah[mf], h0, h1);
                        mma_bf16(acc[mf][nf], ah[mf], l0, l1);
                        mma_bf16(acc[mf][nf], al[mf], h0, h1);
                    }
                }
            }
        }
        __syncthreads();
    }
}

// ---- merged Q/K/V projections: grid.x = 48 (mode = blockIdx.x >> 4) ----
__global__ void __launch_bounds__(256, 2) gemm_qkv(
    const __nv_bfloat16* __restrict__ Ah, const __nv_bfloat16* __restrict__ Al,
    const __nv_bfloat16* __restrict__ Wh, const __nv_bfloat16* __restrict__ Wl,
    const float2* __restrict__ rope, OutPtrs op)
{
    extern __shared__ char smc[];
    const uint32_t sbase = smem_u32(smc);
    const int tid  = threadIdx.x;
    const int wid  = tid >> 5;
    const int lane = tid & 31;
    const int wm   = wid & 3;
    const int wn   = wid >> 2;
    const int mode = blockIdx.x >> 4;              // 0=Q 1=K 2=V
    const int col0 = (blockIdx.x & 15) * 128;
    const int row0 = blockIdx.y * 128;
    const size_t wo = (size_t)mode * ND * ND;

    float acc[2][8][4];
#pragma unroll
    for (int mf = 0; mf < 2; ++mf)
#pragma unroll
        for (int nf = 0; nf < 8; ++nf)
#pragma unroll
            for (int e = 0; e < 4; ++e) acc[mf][nf][e] = 0.f;

    mma_mainloop(acc, Ah + (size_t)row0 * ND, Al + (size_t)row0 * ND,
                 Wh + wo + (size_t)col0 * ND, Wl + wo + (size_t)col0 * ND,
                 sbase, tid, wm, wn, lane);

    __nv_bfloat16* Ch = (mode == 0) ? op.qh : (mode == 1) ? op.kh : op.vth;
    __nv_bfloat16* Cl = (mode == 0) ? op.ql : (mode == 1) ? op.kl : op.vtl;

#pragma unroll
    for (int mf = 0; mf < 2; ++mf) {
        const int mrow = row0 + wm * 32 + mf * 16 + (lane >> 2);
#pragma unroll
        for (int rr = 0; rr < 2; ++rr) {
            const int m  = mrow + rr * 8;
            const int bb = m >> 11, ss = m & 2047;
#pragma unroll
            for (int nf = 0; nf < 8; ++nf) {
                const int cloc = wn * 64 + nf * 8 + ((lane & 3) << 1);
                const int col  = col0 + cloc;
                const int h    = col >> 7;
                const int d    = cloc & 127;
                float v0 = acc[mf][nf][rr * 2 + 0];
                float v1 = acc[mf][nf][rr * 2 + 1];
                if (mode == 2) {
                    size_t vb = ((size_t)(bb * NH + h) * DH + d) * NS + ss;
                    __nv_bfloat16 h0 = __float2bfloat16_rn(v0);
                    __nv_bfloat16 h1 = __float2bfloat16_rn(v1);
                    Ch[vb]      = h0;
                    Ch[vb + NS] = h1;
                    Cl[vb]      = __float2bfloat16_rn(v0 - __bfloat162float(h0));
                    Cl[vb + NS] = __float2bfloat16_rn(v1 - __bfloat162float(h1));
                } else {
                    size_t ob = (((size_t)(bb * NH + h) * NS + ss) << 7) + d;
                    // d even, so (d&63) even: one aligned float4 covers both
                    // (cos_e, sin_e, cos_o, sin_o) — same values sincosf gave.
                    float4 cs = *(const float4*)(rope + (size_t)ss * 64 + (d & 63));
                    float o0 = v0 * cs.x - v1 * cs.y;
                    float o1 = v1 * cs.z + v0 * cs.w;
                    if (mode == 0) { o0 *= QSCALE; o1 *= QSCALE; }
                    uint32_t hp, lp;
                    hilo2(o0, o1, hp, lp);
                    *reinterpret_cast<uint32_t*>(Ch + ob) = hp;
                    *reinterpret_cast<uint32_t*>(Cl + ob) = lp;
                }
            }
        }
    }
}

// ---- final projection: fp32 row-major out ----
__global__ void __launch_bounds__(256, 2) gemm_out(
    const __nv_bfloat16* __restrict__ Ah, const __nv_bfloat16* __restrict__ Al,
    const __nv_bfloat16* __restrict__ Wh, const __nv_bfloat16* __restrict__ Wl,
    float* __restrict__ C)
{
    extern __shared__ char smc[];
    const uint32_t sbase = smem_u32(smc);
    const int tid  = threadIdx.x;
    const int wid  = tid >> 5;
    const int lane = tid & 31;
    const int wm   = wid & 3;
    const int wn   = wid >> 2;
    const int col0 = blockIdx.x * 128;
    const int row0 = blockIdx.y * 128;

    float acc[2][8][4];
#pragma unroll
    for (int mf = 0; mf < 2; ++mf)
#pragma unroll
        for (int nf = 0; nf < 8; ++nf)
#pragma unroll
            for (int e = 0; e < 4; ++e) acc[mf][nf][e] = 0.f;

    mma_mainloop(acc, Ah + (size_t)row0 * ND, Al + (size_t)row0 * ND,
                 Wh + (size_t)col0 * ND, Wl + (size_t)col0 * ND,
                 sbase, tid, wm, wn, lane);

#pragma unroll
    for (int mf = 0; mf < 2; ++mf) {
        const int mrow = row0 + wm * 32 + mf * 16 + (lane >> 2);
#pragma unroll
        for (int rr = 0; rr < 2; ++rr) {
            const int m = mrow + rr * 8;
#pragma unroll
            for (int nf = 0; nf < 8; ++nf) {
                const int col = col0 + wn * 64 + nf * 8 + ((lane & 3) << 1);
                *(float2*)(C + (size_t)m * ND + col) =
                    make_float2(acc[mf][nf][rr * 2 + 0], acc[mf][nf][rr * 2 + 1]);
            }
        }
    }
}

// ======================= flash attention (mma.sync) ========================
// Paired q-tiles per CTA for load balance: CTA bx handles qt = NQT-1-bx
// (heavy) then qt = bx (light) -> uniform work, grid 256 CTAs.
#define NQT (NS / 128)                // 16
#define QPB 272
#define VPB 144
#define OQH 0
#define OQL (OQH + 128*QPB)
#define OKH (OQL + 128*QPB)
#define OKL (OKH + 2*64*QPB)
#define OVH (OKL + 2*64*QPB)
#define OVL (OVH + 2*128*VPB)
#define FSMEM (OVL + 2*128*VPB)       // 212992

__global__ void __launch_bounds__(256, 1) flash_mma(
    const __nv_bfloat16* __restrict__ Qh, const __nv_bfloat16* __restrict__ Ql,
    const __nv_bfloat16* __restrict__ Kh, const __nv_bfloat16* __restrict__ Kl,
    const __nv_bfloat16* __restrict__ Vth, const __nv_bfloat16* __restrict__ Vtl,
    __nv_bfloat16* __restrict__ Oh, __nv_bfloat16* __restrict__ Ol)
{
    extern __shared__ char smc[];
    const uint32_t sb = smem_u32(smc);
    const int tid = threadIdx.x, wid = tid >> 5, lane = tid & 31;
    const int h  = blockIdx.y, b = blockIdx.z;
    const size_t ho = (size_t)(b * NH + h) * NS * DH;

    const uint32_t a_off  = (uint32_t)((wid * 16 + (lane & 15)) * QPB + (lane >> 4) * 16);
    const uint32_t b_row  = (uint32_t)((lane & 7) + ((lane >> 4) << 3));
    const uint32_t b_koff = (uint32_t)(((lane >> 3) & 1) * 16);

    auto loadKV = [&](int buf, int n0) {
#pragma unroll
        for (int t = 0; t < 8; ++t) {
            int id  = tid + t * 256;
            int arr = id >> 10;
            int rem = id & 1023;
            int r = rem >> 4, c = rem & 15;
            uint32_t so = sb + (arr ? OKL : OKH) + buf * (64 * QPB) + r * QPB + c * 16;
            const __nv_bfloat16* g = (arr ? Kl : Kh) + ho + (size_t)(n0 + r) * DH + c * 8;
            cpa16(so, g);
        }
#pragma unroll
        for (int t = 0; t < 8; ++t) {
            int id  = tid + t * 256;
            int arr = id >> 10;
            int rem = id & 1023;
            int r = rem >> 3, c = rem & 7;
            uint32_t so = sb + (arr ? OVL : OVH) + buf * (128 * VPB) + r * VPB + c * 16;
            const __nv_bfloat16* g = (arr ? Vtl : Vth) + ho + (size_t)r * NS + n0 + c * 8;
            cpa16(so, g);
        }
    };

#pragma unroll 1
    for (int rep = 0; rep < 2; ++rep) {
        const int qt = rep == 0 ? (NQT - 1 - (int)blockIdx.x) : (int)blockIdx.x;
        const int q0 = qt * 128;

        // Q tile for this rep (smem safe: all warps passed the last k-iter sync)
#pragma unroll
        for (int t = 0; t < 16; ++t) {
            int id  = tid + t * 256;
            int arr = id >> 11;
            int rem = id & 2047;
            int r = rem >> 4, c = rem & 15;
            uint32_t so = sb + (arr ? OQL : OQH) + r * QPB + c * 16;
            const __nv_bfloat16* g = (arr ? Ql : Qh) + ho + (size_t)(q0 + r) * DH + c * 8;
            cpa16(so, g);
        }
        loadKV(0, 0);
        CPA_COMMIT();

        const int rmin = q0 + wid * 16;
        float o[16][4];
#pragma unroll
        for (int nf = 0; nf < 16; ++nf)
#pragma unroll
            for (int e = 0; e < 4; ++e) o[nf][e] = 0.f;
        float m0 = -CUDART_INF_F, m1 = -CUDART_INF_F, l0 = 0.f, l1 = 0.f;

        const int niter = q0 / 64 + 2;
        for (int it = 0; it < niter; ++it) {
            const int n0 = it * 64, buf = it & 1;
            if (it + 1 < niter) { loadKV(buf ^ 1, (it + 1) * 64); CPA_COMMIT(); CPA_WAIT1(); }
            else                { CPA_WAIT0(); }
            __syncthreads();

            if (n0 <= rmin + 15) {
                float sc[8][4];
#pragma unroll
                for (int nf = 0; nf < 8; ++nf)
#pragma unroll
                    for (int e = 0; e < 4; ++e) sc[nf][e] = 0.f;

                const uint32_t kh_b = sb + OKH + buf * (64 * QPB) + b_row * QPB + b_koff;
                const uint32_t kl_b = sb + OKL + buf * (64 * QPB) + b_row * QPB + b_koff;
#pragma unroll 4
                for (int t = 0; t < 8; ++t) {
                    uint32_t ah[4], av[4];
                    ldsm4(ah, sb + OQH + a_off + t * 32);
                    ldsm4(av, sb + OQL + a_off + t * 32);
#pragma unroll
                    for (int nf2 = 0; nf2 < 4; ++nf2) {
                        uint32_t bh[4], bl[4];
                        ldsm4(bh, kh_b + nf2 * (16 * QPB) + t * 32);
                        ldsm4(bl, kl_b + nf2 * (16 * QPB) + t * 32);
                        mma_bf16(sc[2*nf2],   ah, bh[0], bh[1]);
                        mma_bf16(sc[2*nf2],   ah, bl[0], bl[1]);
                        mma_bf16(sc[2*nf2],   av, bh[0], bh[1]);
                        mma_bf16(sc[2*nf2+1], ah, bh[2], bh[3]);
                        mma_bf16(sc[2*nf2+1], ah, bl[2], bl[3]);
                        mma_bf16(sc[2*nf2+1], av, bh[2], bh[3]);
                    }
                }

                const int r_lo = rmin + (lane >> 2);
                if (n0 + 63 > rmin) {
#pragma unroll
                    for (int nf = 0; nf < 8; ++nf) {
                        int cbase = n0 + nf * 8 + ((lane & 3) << 1);
#pragma unroll
                        for (int e = 0; e < 4; ++e) {
                            int col = cbase + (e & 1);
                            int row = r_lo + ((e >> 1) << 3);
                            if (col > row) sc[nf][e] = -CUDART_INF_F;
                        }
                    }
                }

                float mx0 = -CUDART_INF_F, mx1 = -CUDART_INF_F;
#pragma unroll
                for (int nf = 0; nf < 8; ++nf) {
                    mx0 = fmaxf(mx0, fmaxf(sc[nf][0], sc[nf][1]));
                    mx1 = fmaxf(mx1, fmaxf(sc[nf][2], sc[nf][3]));
                }
                mx0 = fmaxf(mx0, __shfl_xor_sync(0xffffffffu, mx0, 1));
                mx0 = fmaxf(mx0, __shfl_xor_sync(0xffffffffu, mx0, 2));
                mx1 = fmaxf(mx1, __shfl_xor_sync(0xffffffffu, mx1, 1));
                mx1 = fmaxf(mx1, __shfl_xor_sync(0xffffffffu, mx1, 2));
                float mn0 = fmaxf(m0, mx0), mn1 = fmaxf(m1, mx1);
                float al0 = __expf(m0 - mn0), al1 = __expf(m1 - mn1);
                float rs0 = 0.f, rs1 = 0.f;
#pragma unroll
                for (int nf = 0; nf < 8; ++nf) {
                    sc[nf][0] = __expf(sc[nf][0] - mn0);
                    sc[nf][1] = __expf(sc[nf][1] - mn0);
                    sc[nf][2] = __expf(sc[nf][2] - mn1);
                    sc[nf][3] = __expf(sc[nf][3] - mn1);
                    rs0 += sc[nf][0] + sc[nf][1];
                    rs1 += sc[nf][2] + sc[nf][3];
                }
                rs0 += __shfl_xor_sync(0xffffffffu, rs0, 1);
                rs0 += __shfl_xor_sync(0xffffffffu, rs0, 2);
                rs1 += __shfl_xor_sync(0xffffffffu, rs1, 1);
                rs1 += __shfl_xor_sync(0xffffffffu, rs1, 2);
                l0 = l0 * al0 + rs0;  l1 = l1 * al1 + rs1;
                m0 = mn0;             m1 = mn1;
#pragma unroll
                for (int nf = 0; nf < 16; ++nf) {
                    o[nf][0] *= al0; o[nf][1] *= al0;
                    o[nf][2] *= al1; o[nf][3] *= al1;
                }

                const uint32_t vh_b = sb + OVH + buf * (128 * VPB) + b_row * VPB + b_koff;
                const uint32_t vl_b = sb + OVL + buf * (128 * VPB) + b_row * VPB + b_koff;
#pragma unroll
                for (int t = 0; t < 4; ++t) {
                    uint32_t pah[4], pal[4];
                    hilo2(sc[2*t][0],   sc[2*t][1],   pah[0], pal[0]);
                    hilo2(sc[2*t][2],   sc[2*t][3],   pah[1], pal[1]);
                    hilo2(sc[2*t+1][0], sc[2*t+1][1], pah[2], pal[2]);
                    hilo2(sc[2*t+1][2], sc[2*t+1][3], pah[3], pal[3]);
#pragma unroll
                    for (int nd2 = 0; nd2 < 8; ++nd2) {
                        uint32_t vh[4], vl[4];
                        ldsm4(vh, vh_b + nd2 * (16 * VPB) + t * 32);
                        ldsm4(vl, vl_b + nd2 * (16 * VPB) + t * 32);
                        mma_bf16(o[2*nd2],   pah, vh[0], vh[1]);
                        mma_bf16(o[2*nd2],   pah, vl[0], vl[1]);
                        mma_bf16(o[2*nd2],   pal, vh[0], vh[1]);
                        mma_bf16(o[2*nd2+1], pah, vh[2], vh[3]);
                        mma_bf16(o[2*nd2+1], pah, vl[2], vl[3]);
                        mma_bf16(o[2*nd2+1], pal, vh[2], vh[3]);
                    }
                }
            }
            __syncthreads();
        }

        const float il0 = 1.f / l0, il1 = 1.f / l1;
        const int srow = rmin + (lane >> 2);
        const int dq   = (lane & 3) << 1;
#pragma unroll
        for (int nf = 0; nf < 16; ++nf) {
            int d = nf * 8 + dq;
            size_t base = (size_t)(b * NS) * ND + (size_t)h * DH + d;
            uint32_t hp, lp;
            hilo2(o[nf][0] * il0, o[nf][1] * il0, hp, lp);
            *reinterpret_cast<uint32_t*>(Oh + base + (size_t)srow * ND) = hp;
            *reinterpret_cast<uint32_t*>(Ol + base + (size_t)srow * ND) = lp;
            hilo2(o[nf][2] * il1, o[nf][3] * il1, hp, lp);
            *reinterpret_cast<uint32_t*>(Oh + base + (size_t)(srow + 8) * ND) = hp;
            *reinterpret_cast<uint32_t*>(Ol + base + (size_t)(srow + 8) * ND) = lp;
        }
    }
}

// ---------------------------------------------------------------------------
extern "C" void kernel_launch(void* const* d_in, const int* in_sizes, int n_in,
                              void* d_out, int out_size) {
    const float* x  = (const float*)d_in[0];
    const float* Wq = (const float*)d_in[1];
    const float* Wk = (const float*)d_in[2];
    const float* Wv = (const float*)d_in[3];
    const float* Wo = (const float*)d_in[4];

    __nv_bfloat16 *xh, *xl, *wh, *wl, *qh, *ql, *kh, *kl, *vth, *vtl;
    float2* rp;
    cudaGetSymbolAddress((void**)&xh,  g_xh);
    cudaGetSymbolAddress((void**)&xl,  g_xl);
    cudaGetSymbolAddress((void**)&wh,  g_wh);
    cudaGetSymbolAddress((void**)&wl,  g_wl);
    cudaGetSymbolAddress((void**)&qh,  g_qh);
    cudaGetSymbolAddress((void**)&ql,  g_ql);
    cudaGetSymbolAddress((void**)&kh,  g_kh);
    cudaGetSymbolAddress((void**)&kl,  g_kl);
    cudaGetSymbolAddress((void**)&vth, g_vth);
    cudaGetSymbolAddress((void**)&vtl, g_vtl);
    cudaGetSymbolAddress((void**)&rp,  g_rope);

    cudaFuncSetAttribute(gemm_qkv, cudaFuncAttributeMaxDynamicSharedMemorySize, GSMEM);
    cudaFuncSetAttribute(gemm_out, cudaFuncAttributeMaxDynamicSharedMemorySize, GSMEM);
    cudaFuncSetAttribute(flash_mma, cudaFuncAttributeMaxDynamicSharedMemorySize, FSMEM);

    OutPtrs op{qh, ql, kh, kl, vth, vtl};

    const int actblocks = NM * ND / (256 * 4);

    // Independent prep: rope table + activation split + weight transpose-splits.
    rope_table<<<NS * 64 / 256, 256>>>(rp);
    split_act<<<actblocks, 256>>>(x, xh, xl);
    split_wT4<<<dim3(ND / 32, ND / 32, 4), dim3(32, 8)>>>(Wq, Wk, Wv, Wo, wh, wl);

    // Merged Q/K/V projections (one launch, 1536 CTAs).
    gemm_qkv<<<dim3(48, NM / 128), 256, GSMEM>>>(xh, xl, wh, wl, rp, op);

    // Flash attention: paired q-tiles, 256 CTAs; writes bf16 hi/lo into xh/xl.
    flash_mma<<<dim3(NQT / 2, NH, NB), 256, FSMEM>>>(qh, ql, kh, kl, vth, vtl, xh, xl);

    // Final projection (weight index 3).
    gemm_out<<<dim3(ND / 128, NM / 128), 256, GSMEM>>>(
        xh, xl, wh + (size_t)3 * ND * ND, wl + (size_t)3 * ND * ND, (float*)d_out);
}